// round 11
// baseline (speedup 1.0000x reference)
#include <cuda_runtime.h>
#include <cuda_bf16.h>

// Problem constants (fixed by reference setup_inputs)
#define HH   1024
#define WW   1024
#define NC   8
#define NCOL (WW * NC)      // 8192 flat columns in [y][x][c] layout
#define NSEG 32
#define SEGH (HH / NSEG)    // 32
#define NPOOL 7

// Scratch: SAT in channel-last layout [y][x][c], fp32. 32 MB (fits L2).
__device__ float g_sat[(size_t)HH * NCOL];
// Decoupled-lookback links per (seg, flat col):
//   {float_bits:32 | flags} flags: bit0 = aggregate ready, bit1 = inclusive.
__device__ unsigned long long g_link[NSEG * NCOL];   // 2 MB
// Row-completion counter (fused pipeline). Reset by pool_kernel for the next
// replay (stream order guarantees no race).
__device__ unsigned int g_rows_done;

// ---------------------------------------------------------------------------
// Fused pass 1+2. Blocks 0..1023: inclusive row scan for y = bid (identical
// to the best-measured 14.0us rowscan), then publish row completion.
// Blocks 1024..2047: column-scan chunk (seg, chunk); waits until all rows
// < 32*(seg+1) are complete (this also guarantees the g_link entries of all
// segs <= seg were reset this run), then runs decoupled-lookback column scan.
// Dependencies point strictly to lower block ids -> deadlock-free.
// ---------------------------------------------------------------------------
__global__ void __launch_bounds__(256) satfused_kernel(const float* __restrict__ in) {
    __shared__ float wsum[NC][8];
    __shared__ float sbuf[256 * 33];      // padded transpose buffer (33 KB)

    const int t = threadIdx.x;

    if (blockIdx.x < HH) {
        // =================== rowscan part ===================
        const int y    = blockIdx.x;
        const int lane = t & 31;
        const int wid  = t >> 5;

        // Reset lookback links: 262144 entries / 1024 rows = 256 each.
        // (Entry (seg,f) is reset by a row block of that same seg.)
        g_link[(size_t)y * 256 + t] = 0ull;

        // Load 4 consecutive x per channel; sequential in-register prefix.
        float4 v[NC];
        float  tot[NC], excl[NC];
        #pragma unroll
        for (int c = 0; c < NC; ++c) {
            v[c] = ((const float4*)(in + (size_t)c * (HH * WW) + (size_t)y * WW))[t];
            v[c].y += v[c].x;
            v[c].z += v[c].y;
            v[c].w += v[c].z;
            tot[c] = v[c].w;
        }

        // Warp inclusive scan of per-thread totals; derive exclusive offset.
        #pragma unroll
        for (int c = 0; c < NC; ++c) {
            float s = tot[c];
            #pragma unroll
            for (int d = 1; d < 32; d <<= 1) {
                float nb = __shfl_up_sync(0xffffffffu, s, d);
                if (lane >= d) s += nb;
            }
            excl[c] = s - tot[c];
            if (lane == 31) wsum[c][wid] = s;
        }
        __syncthreads();

        // Warp 0 scans the 8 warp totals per channel (width-8 groups).
        if (wid == 0) {
            #pragma unroll
            for (int c = 0; c < NC; ++c) {
                float w = (lane < 8) ? wsum[c][lane] : 0.f;
                #pragma unroll
                for (int d = 1; d < 8; d <<= 1) {
                    float nb = __shfl_up_sync(0xffffffffu, w, d);
                    if ((lane & 7) >= d) w += nb;
                }
                if (lane < 8) wsum[c][lane] = w;
            }
        }
        __syncthreads();

        // Final values -> padded smem in [x][c] order: idx = 33*t + 8*i + c.
        #pragma unroll
        for (int c = 0; c < NC; ++c) {
            float off = excl[c] + (wid ? wsum[c][wid - 1] : 0.f);
            sbuf[33 * t + c]      = v[c].x + off;
            sbuf[33 * t + 8 + c]  = v[c].y + off;
            sbuf[33 * t + 16 + c] = v[c].z + off;
            sbuf[33 * t + 24 + c] = v[c].w + off;
        }
        __syncthreads();

        // Coalesced float4 stores: output float index o -> smem idx = o + o/32.
        float4* out4 = (float4*)(g_sat + (size_t)y * NCOL);
        #pragma unroll
        for (int j = 0; j < 8; ++j) {
            const int o   = (j * 256 + t) * 4;
            const int idx = o + (o >> 5);
            out4[j * 256 + t] = make_float4(sbuf[idx], sbuf[idx + 1],
                                            sbuf[idx + 2], sbuf[idx + 3]);
        }

        // Publish: row y complete (SAT row + link resets visible first).
        __threadfence();
        __syncthreads();
        if (t == 0) atomicAdd(&g_rows_done, 1u);

    } else {
        // =================== colscan part ===================
        const int b     = blockIdx.x - HH;       // 0..1023
        const int seg   = b >> 5;                // 32 chunks per seg
        const int chunk = b & 31;
        const int f     = chunk * 256 + t;

        // Wait for all rows < 32*(seg+1) (covers data + link resets of all
        // segs <= seg). Single poller per block.
        if (t == 0) {
            const unsigned need = 32u * (unsigned)(seg + 1);
            while (atomicAdd(&g_rows_done, 0u) < need) { }
        }
        __syncthreads();
        __threadfence();   // acquire

        float* base = g_sat + (size_t)seg * SEGH * NCOL + f;

        // Local inclusive prefix over the 32 segment rows (reg-resident).
        float pref[SEGH];
        float s = 0.f;
        #pragma unroll
        for (int k = 0; k < SEGH; ++k) {
            s += __ldcg(base + (size_t)k * NCOL);
            pref[k] = s;
        }

        // Publish local aggregate immediately (flag = 1).
        if (seg < NSEG - 1) {
            unsigned long long agg =
                ((unsigned long long)__float_as_uint(s) << 32) | 1ull;
            atomicExch(&g_link[(size_t)seg * NCOL + f], agg);
        }

        // Lookback: walk predecessors, summing aggregates, stop at inclusive.
        float off = 0.f;
        for (int i = seg - 1; i >= 0; --i) {
            unsigned long long u;
            do {
                u = atomicAdd(&g_link[(size_t)i * NCOL + f], 0ull);
            } while (!(u & 1ull));
            off += __uint_as_float((unsigned)(u >> 32));
            if (u & 2ull) break;   // that value was inclusive -> done
        }

        // Publish inclusive prefix (flag = 3).
        if (seg < NSEG - 1) {
            unsigned long long inc =
                ((unsigned long long)__float_as_uint(off + s) << 32) | 3ull;
            atomicExch(&g_link[(size_t)seg * NCOL + f], inc);
        }

        // Finalize in place.
        #pragma unroll
        for (int k = 0; k < SEGH; ++k)
            __stcg(base + (size_t)k * NCOL, pref[k] + off);
    }
}

// ---------------------------------------------------------------------------
// Pass 3: adaptive 7x7 ROI pooling + final mean. One warp per ROI.
// g_sat holds inclusive SAT; padded sat(y,x) = g_sat[y-1][x-1] (0 at borders).
// Also resets g_rows_done for the next graph replay.
// ---------------------------------------------------------------------------
__device__ __forceinline__ void load8(int y, int x, float v[8]) {
    if (y > 0 && x > 0) {
        const float4* p = (const float4*)(g_sat + ((size_t)(y - 1) * WW + (x - 1)) * NC);
        float4 a = p[0], b = p[1];
        v[0] = a.x; v[1] = a.y; v[2] = a.z; v[3] = a.w;
        v[4] = b.x; v[5] = b.y; v[6] = b.z; v[7] = b.w;
    } else {
        #pragma unroll
        for (int c = 0; c < 8; ++c) v[c] = 0.f;
    }
}

__global__ void __launch_bounds__(256) pool_kernel(const int* __restrict__ rois,
                                                   float* __restrict__ out, int n) {
    if (blockIdx.x == 0 && threadIdx.x == 0)
        g_rows_done = 0;     // reset for next replay (stream-ordered)

    const int warp = (blockIdx.x * blockDim.x + threadIdx.x) >> 5;
    const int lane = threadIdx.x & 31;
    if (warp >= n) return;

    // rois is int32 [n,4]
    const int4 R = ((const int4*)rois)[warp];
    const int ymin = R.x >> 5;            // // FEAT_STRIDE (=32)
    const int xmin = R.y >> 5;
    const int ymax = (R.z >> 5) + 1;      // exclusive
    const int xmax = (R.w >> 5) + 1;
    const int leny = ymax - ymin;
    const int lenx = xmax - xmin;

    float acc[8];
    #pragma unroll
    for (int c = 0; c < 8; ++c) acc[c] = 0.f;

    for (int bin = lane; bin < 49; bin += 32) {
        const int i = bin / 7;
        const int j = bin - i * 7;
        const int ylo = ymin + (i * leny) / NPOOL;
        const int yhi = ymin + ((i + 1) * leny + NPOOL - 1) / NPOOL;
        const int xlo = xmin + (j * lenx) / NPOOL;
        const int xhi = xmin + ((j + 1) * lenx + NPOOL - 1) / NPOOL;

        float Shh[8], Slh[8], Shl[8], Sll[8];
        load8(yhi, xhi, Shh);
        load8(ylo, xhi, Slh);
        load8(yhi, xlo, Shl);
        load8(ylo, xlo, Sll);

        const int   area = (yhi - ylo) * (xhi - xlo);
        const float w    = 1.f / (float)area;
        #pragma unroll
        for (int c = 0; c < 8; ++c)
            acc[c] += w * ((Shh[c] - Slh[c]) - (Shl[c] - Sll[c]));
    }

    #pragma unroll
    for (int c = 0; c < 8; ++c) {
        #pragma unroll
        for (int d = 16; d; d >>= 1)
            acc[c] += __shfl_xor_sync(0xffffffffu, acc[c], d);
    }

    if (lane == 0) {
        const float inv49 = 1.f / 49.f;
        float4 o0 = make_float4(acc[0] * inv49, acc[1] * inv49, acc[2] * inv49, acc[3] * inv49);
        float4 o1 = make_float4(acc[4] * inv49, acc[5] * inv49, acc[6] * inv49, acc[7] * inv49);
        float4* o = (float4*)(out + (size_t)warp * 8);
        o[0] = o0;
        o[1] = o1;
    }
}

// ---------------------------------------------------------------------------
extern "C" void kernel_launch(void* const* d_in, const int* in_sizes, int n_in,
                              void* d_out, int out_size) {
    const float* conv = (const float*)d_in[0];   // [8,1024,1024] fp32
    const int*   rois = (const int*)d_in[1];     // [n,4] int32
    float*       out  = (float*)d_out;           // [n,8] fp32
    const int n = in_sizes[1] / 4;

    satfused_kernel<<<HH + NSEG * (NCOL / 256), 256>>>(conv);
    pool_kernel    <<<(n + 7) / 8, 256>>>(rois, out, n);
}